// round 8
// baseline (speedup 1.0000x reference)
#include <cuda_runtime.h>
#include <cuda_bf16.h>
#include <cuda_fp16.h>
#include <cstdint>

#define NN 50000
#define EE 800000
#define NBLK 196   // ceil(NN/256)

// ---------------- device scratch ----------------
__device__ float g_hA[NN * 128];      // layer-1 out; reused as layer-3 self[NN*64]
__device__ float g_hB[NN * 128];      // layer-2 out
__device__ float g_neigh[NN * 128];   // aggregated neighbor features (fp32)
__device__ __half g_h16[NN * 128];    // fp16 gather mirror: x16 -> hA16 -> p16 (reused)
__device__ int   g_deg[NN];
__device__ int   g_off[NN + 1];
__device__ int   g_cur[NN];
__device__ int   g_csr[EE];
__device__ int   g_bsum[256];
__device__ int   g_boff[256];
__device__ __nv_bfloat16 g_Bhi[3 * 128 * 256];
__device__ __nv_bfloat16 g_Blo[3 * 128 * 256];

// ---------------- helpers ----------------
__device__ __forceinline__ uint32_t smem_u32(const void* p) {
    uint32_t a;
    asm("{ .reg .u64 t; cvta.to.shared.u64 t, %1; cvt.u32.u64 %0, t; }" : "=r"(a) : "l"(p));
    return a;
}
__device__ __forceinline__ uint32_t pack_bf16(float x, float y) {
    __nv_bfloat162 t = __floats2bfloat162_rn(x, y);
    return *reinterpret_cast<uint32_t*>(&t);
}
__device__ __forceinline__ void mma_bf16(float* d, const uint32_t* a, const uint32_t* b) {
    asm volatile(
        "mma.sync.aligned.m16n8k16.row.col.f32.bf16.bf16.f32 "
        "{%0,%1,%2,%3}, {%4,%5,%6,%7}, {%8,%9}, {%0,%1,%2,%3};"
        : "+f"(d[0]), "+f"(d[1]), "+f"(d[2]), "+f"(d[3])
        : "r"(a[0]), "r"(a[1]), "r"(a[2]), "r"(a[3]), "r"(b[0]), "r"(b[1]));
}
__device__ __forceinline__ void ldsm_x4(uint32_t* r, uint32_t addr) {
    asm volatile("ldmatrix.sync.aligned.m8n8.x4.shared.b16 {%0,%1,%2,%3}, [%4];"
                 : "=r"(r[0]), "=r"(r[1]), "=r"(r[2]), "=r"(r[3]) : "r"(addr));
}

// ---------------- B preparation: W (fp32) -> transposed bf16 hi/lo ----------------
__global__ void prep_B_kernel(const float* __restrict__ W1, const float* __restrict__ W2,
                              __nv_bfloat16* __restrict__ bhi, __nv_bfloat16* __restrict__ blo,
                              int mode) {
    int K = (mode == 0) ? 256 : 128;
    int idx = blockIdx.x * blockDim.x + threadIdx.x;
    if (idx >= 128 * K) return;
    int n = idx / K, k = idx % K;
    float w;
    if (mode == 0) w = (k < 128) ? W1[k * 128 + n] : W2[(k - 128) * 128 + n];
    else           w = (n < 64) ? W1[k * 64 + n] : W2[k * 64 + (n - 64)];
    __nv_bfloat16 hi = __float2bfloat16(w);
    bhi[idx] = hi;
    blo[idx] = __float2bfloat16(w - __bfloat162float(hi));
}

// ---------------- fp32 -> fp16 convert (vectorized, 16B loads) ----------------
__global__ void conv16_kernel(const float4* __restrict__ src, uint2* __restrict__ dst, int n4) {
    int i = blockIdx.x * blockDim.x + threadIdx.x;
    if (i < n4) {
        float4 v = src[i];
        __half2 h0 = __floats2half2_rn(v.x, v.y);
        __half2 h1 = __floats2half2_rn(v.z, v.w);
        dst[i] = make_uint2(*reinterpret_cast<uint32_t*>(&h0), *reinterpret_cast<uint32_t*>(&h1));
    }
}

// ---------------- CSR build ----------------
__global__ void zero_kernel() {
    int i = blockIdx.x * blockDim.x + threadIdx.x;
    if (i < NN) g_deg[i] = 0;
}
__global__ void count_kernel(const int* __restrict__ dst) {
    int e = blockIdx.x * blockDim.x + threadIdx.x;
    if (e < EE) atomicAdd(&g_deg[dst[e]], 1);
}
__global__ void scan_partials() {
    __shared__ int sh[256];
    int t = threadIdx.x;
    int i = blockIdx.x * 256 + t;
    sh[t] = (i < NN) ? g_deg[i] : 0;
    __syncthreads();
    for (int o = 128; o > 0; o >>= 1) {
        if (t < o) sh[t] += sh[t + o];
        __syncthreads();
    }
    if (t == 0) g_bsum[blockIdx.x] = sh[0];
}
__global__ void scan_bsums() {
    __shared__ int sh[256];
    int t = threadIdx.x;
    int v = (t < NBLK) ? g_bsum[t] : 0;
    sh[t] = v;
    __syncthreads();
    for (int o = 1; o < 256; o <<= 1) {
        int x = (t >= o) ? sh[t - o] : 0;
        __syncthreads();
        sh[t] += x;
        __syncthreads();
    }
    if (t < NBLK) g_boff[t] = sh[t] - v;   // exclusive
}
__global__ void scan_final() {
    __shared__ int sh[256];
    int t = threadIdx.x;
    int i = blockIdx.x * 256 + t;
    int v = (i < NN) ? g_deg[i] : 0;
    sh[t] = v;
    __syncthreads();
    for (int o = 1; o < 256; o <<= 1) {
        int x = (t >= o) ? sh[t - o] : 0;
        __syncthreads();
        sh[t] += x;
        __syncthreads();
    }
    if (i <= NN) g_off[i] = g_boff[blockIdx.x] + sh[t] - v;  // exclusive; g_off[NN]=EE
    if (i < NN) g_cur[i] = 0;
}
__global__ void fill_kernel(const int* __restrict__ src, const int* __restrict__ dst) {
    int e = blockIdx.x * blockDim.x + threadIdx.x;
    if (e < EE) {
        int d = dst[e];
        int pos = g_off[d] + atomicAdd(&g_cur[d], 1);
        g_csr[pos] = src[e];
    }
}

// ---------------- mean aggregation from fp16 mirror (128-dim), unroll-4 ----------------
__global__ void agg_h16_kernel(const __half* __restrict__ h16, float* __restrict__ neigh) {
    int gt = blockIdx.x * blockDim.x + threadIdx.x;
    int node = gt >> 5;
    int lane = gt & 31;
    if (node >= NN) return;
    int s = g_off[node], e = g_off[node + 1];
    float a0 = 0.f, a1 = 0.f, a2 = 0.f, a3 = 0.f;
    int j = s;
    for (; j + 4 <= e; j += 4) {
        int i0 = g_csr[j], i1 = g_csr[j + 1], i2 = g_csr[j + 2], i3 = g_csr[j + 3];
        uint2 v0 = *reinterpret_cast<const uint2*>(h16 + (size_t)i0 * 128 + lane * 4);
        uint2 v1 = *reinterpret_cast<const uint2*>(h16 + (size_t)i1 * 128 + lane * 4);
        uint2 v2 = *reinterpret_cast<const uint2*>(h16 + (size_t)i2 * 128 + lane * 4);
        uint2 v3 = *reinterpret_cast<const uint2*>(h16 + (size_t)i3 * 128 + lane * 4);
        float2 f;
        f = __half22float2(*reinterpret_cast<__half2*>(&v0.x)); a0 += f.x; a1 += f.y;
        f = __half22float2(*reinterpret_cast<__half2*>(&v0.y)); a2 += f.x; a3 += f.y;
        f = __half22float2(*reinterpret_cast<__half2*>(&v1.x)); a0 += f.x; a1 += f.y;
        f = __half22float2(*reinterpret_cast<__half2*>(&v1.y)); a2 += f.x; a3 += f.y;
        f = __half22float2(*reinterpret_cast<__half2*>(&v2.x)); a0 += f.x; a1 += f.y;
        f = __half22float2(*reinterpret_cast<__half2*>(&v2.y)); a2 += f.x; a3 += f.y;
        f = __half22float2(*reinterpret_cast<__half2*>(&v3.x)); a0 += f.x; a1 += f.y;
        f = __half22float2(*reinterpret_cast<__half2*>(&v3.y)); a2 += f.x; a3 += f.y;
    }
    for (; j < e; j++) {
        int sidx = g_csr[j];
        uint2 v = *reinterpret_cast<const uint2*>(h16 + (size_t)sidx * 128 + lane * 4);
        float2 f0 = __half22float2(*reinterpret_cast<__half2*>(&v.x));
        float2 f1 = __half22float2(*reinterpret_cast<__half2*>(&v.y));
        a0 += f0.x; a1 += f0.y; a2 += f1.x; a3 += f1.y;
    }
    float inv = 1.0f / (float)max(e - s, 1);
    *reinterpret_cast<float4*>(neigh + (size_t)node * 128 + lane * 4) =
        make_float4(a0 * inv, a1 * inv, a2 * inv, a3 * inv);
}

// ---------------- layer-3 final: out = self + mean(proj16[src]), unroll-4 ----------------
__global__ void agg3_h16_kernel(const __half* __restrict__ p16, const float* __restrict__ self,
                                float* __restrict__ out) {
    int gt = blockIdx.x * blockDim.x + threadIdx.x;
    int node = gt >> 5;
    int lane = gt & 31;
    if (node >= NN) return;
    int s = g_off[node], e = g_off[node + 1];
    float a0 = 0.f, a1 = 0.f;
    int j = s;
    for (; j + 4 <= e; j += 4) {
        int i0 = g_csr[j], i1 = g_csr[j + 1], i2 = g_csr[j + 2], i3 = g_csr[j + 3];
        uint32_t v0 = *reinterpret_cast<const uint32_t*>(p16 + (size_t)i0 * 64 + lane * 2);
        uint32_t v1 = *reinterpret_cast<const uint32_t*>(p16 + (size_t)i1 * 64 + lane * 2);
        uint32_t v2 = *reinterpret_cast<const uint32_t*>(p16 + (size_t)i2 * 64 + lane * 2);
        uint32_t v3 = *reinterpret_cast<const uint32_t*>(p16 + (size_t)i3 * 64 + lane * 2);
        float2 f;
        f = __half22float2(*reinterpret_cast<__half2*>(&v0)); a0 += f.x; a1 += f.y;
        f = __half22float2(*reinterpret_cast<__half2*>(&v1)); a0 += f.x; a1 += f.y;
        f = __half22float2(*reinterpret_cast<__half2*>(&v2)); a0 += f.x; a1 += f.y;
        f = __half22float2(*reinterpret_cast<__half2*>(&v3)); a0 += f.x; a1 += f.y;
    }
    for (; j < e; j++) {
        int sidx = g_csr[j];
        uint32_t v = *reinterpret_cast<const uint32_t*>(p16 + (size_t)sidx * 64 + lane * 2);
        float2 f = __half22float2(*reinterpret_cast<__half2*>(&v));
        a0 += f.x; a1 += f.y;
    }
    float inv = 1.0f / (float)max(e - s, 1);
    float2 sv = *reinterpret_cast<const float2*>(self + (size_t)node * 64 + lane * 2);
    *reinterpret_cast<float2*>(out + (size_t)node * 64 + lane * 2) =
        make_float2(sv.x + a0 * inv, sv.y + a1 * inv);
}

// ---------------- bf16-split tensor-core GEMM, ldmatrix + double buffer ----------------
// MODE 0: relu*mask, out fp32 128-wide + h16 fp16 mirror (layer 1)
// MODE 1: relu*mask, out fp32 128-wide                      (layer 2)
// MODE 2: layer 3 split: cols<64 -> self fp32 (+bias), cols>=64 -> p16 fp16 (no bias)
template <int KCHUNKS, bool DUAL, int MODE>
__global__ void __launch_bounds__(256, 2)
sage_mma_kernel(const float* __restrict__ A0, const float* __restrict__ A1,
                const __nv_bfloat16* __restrict__ Bhi, const __nv_bfloat16* __restrict__ Blo,
                const float* __restrict__ bias, const float* __restrict__ mask,
                float* __restrict__ out, __half* __restrict__ h16out) {
    constexpr int PAD = 40;
    constexpr int KTOT = KCHUNKS * 32;
    constexpr int BUFH = 128 * PAD;
    extern __shared__ uint16_t sm[];
    uint16_t* sAh = sm;
    uint16_t* sAl = sm + 2 * BUFH;
    uint16_t* sBh = sm + 4 * BUFH;
    uint16_t* sBl = sm + 6 * BUFH;
    const uint32_t base = smem_u32(sm);

    const int tid = threadIdx.x, lane = tid & 31, wid = tid >> 5;
    const int bm = blockIdx.x * 128;
    const int wm = (wid & 3) * 32;
    const int wn = (wid >> 2) * 64;

    float acc[2][8][4];
#pragma unroll
    for (int m = 0; m < 2; m++)
#pragma unroll
        for (int n = 0; n < 8; n++)
#pragma unroll
            for (int i = 0; i < 4; i++) acc[m][n][i] = 0.f;

    float4 pa[4];
    auto loadA = [&](int ch) {
        const float* asrc = DUAL ? (ch < KCHUNKS / 2 ? A0 : A1) : A0;
        int klocal = DUAL ? (ch & (KCHUNKS / 2 - 1)) * 32 : ch * 32;
#pragma unroll
        for (int i = 0; i < 4; i++) {
            int row = (tid >> 3) + i * 32;
            int grow = bm + row;
            pa[i] = (grow < NN)
                ? *reinterpret_cast<const float4*>(asrc + (size_t)grow * 128 + klocal + (tid & 7) * 4)
                : make_float4(0.f, 0.f, 0.f, 0.f);
        }
    };
    auto storeA = [&](int buf) {
#pragma unroll
        for (int i = 0; i < 4; i++) {
            int row = (tid >> 3) + i * 32;
            float4 v = pa[i];
            __nv_bfloat16 hx = __float2bfloat16(v.x);
            __nv_bfloat16 hy = __float2bfloat16(v.y);
            __nv_bfloat16 hz = __float2bfloat16(v.z);
            __nv_bfloat16 hw = __float2bfloat16(v.w);
            uint32_t h01 = pack_bf16(v.x, v.y);
            uint32_t h23 = pack_bf16(v.z, v.w);
            uint32_t l01 = pack_bf16(v.x - __bfloat162float(hx), v.y - __bfloat162float(hy));
            uint32_t l23 = pack_bf16(v.z - __bfloat162float(hz), v.w - __bfloat162float(hw));
            int off = buf * BUFH + row * PAD + (tid & 7) * 4;
            *reinterpret_cast<uint2*>(&sAh[off]) = make_uint2(h01, h23);
            *reinterpret_cast<uint2*>(&sAl[off]) = make_uint2(l01, l23);
        }
    };
    auto stageB = [&](int ch, int buf) {
        int k0 = ch * 32;
#pragma unroll
        for (int j = 0; j < 2; j++) {
            int item = tid + j * 256;
            int n = item >> 2, q = item & 3;
            int soff = n * KTOT + k0 + q * 8;
            uint4 vh = *reinterpret_cast<const uint4*>(Bhi + soff);
            uint4 vl = *reinterpret_cast<const uint4*>(Blo + soff);
            int doff = buf * BUFH + n * PAD + q * 8;
            *reinterpret_cast<uint4*>(&sBh[doff]) = vh;
            *reinterpret_cast<uint4*>(&sBl[doff]) = vl;
        }
    };

    loadA(0);
    storeA(0);
    stageB(0, 0);

    for (int ch = 0; ch < KCHUNKS; ch++) {
        __syncthreads();
        int buf = ch & 1;
        bool more = (ch + 1 < KCHUNKS);
        if (more) loadA(ch + 1);

#pragma unroll
        for (int ks = 0; ks < 2; ks++) {
            uint32_t ah[2][4], al[2][4];
            int arow = wm + (lane & 7) + ((lane >> 3) & 1) * 8;
            int acol = ks * 16 + (lane >> 4) * 8;
#pragma unroll
            for (int m = 0; m < 2; m++) {
                uint32_t aoff = (uint32_t)(buf * BUFH + (arow + m * 16) * PAD + acol) * 2;
                ldsm_x4(ah[m], base + aoff);
                ldsm_x4(al[m], base + (uint32_t)(2 * BUFH) * 2 + aoff);
            }
            int brow = wn + (lane & 7) + ((lane >> 4) & 1) * 8;
            int bcol = ks * 16 + ((lane >> 3) & 1) * 8;
#pragma unroll
            for (int nt2 = 0; nt2 < 4; nt2++) {
                uint32_t bh[4], bl4[4];
                uint32_t boff = (uint32_t)(buf * BUFH + (brow + nt2 * 16) * PAD + bcol) * 2;
                ldsm_x4(bh, base + (uint32_t)(4 * BUFH) * 2 + boff);
                ldsm_x4(bl4, base + (uint32_t)(6 * BUFH) * 2 + boff);
#pragma unroll
                for (int m = 0; m < 2; m++) {
                    mma_bf16(acc[m][nt2 * 2], ah[m], &bh[0]);
                    mma_bf16(acc[m][nt2 * 2], ah[m], &bl4[0]);
                    mma_bf16(acc[m][nt2 * 2], al[m], &bh[0]);
                    mma_bf16(acc[m][nt2 * 2 + 1], ah[m], &bh[2]);
                    mma_bf16(acc[m][nt2 * 2 + 1], ah[m], &bl4[2]);
                    mma_bf16(acc[m][nt2 * 2 + 1], al[m], &bh[2]);
                }
            }
        }
        if (more) { storeA(buf ^ 1); stageB(ch + 1, buf ^ 1); }
    }

    // ---- epilogue ----
#pragma unroll
    for (int m = 0; m < 2; m++) {
        int r0 = bm + wm + m * 16 + (lane >> 2);
#pragma unroll
        for (int nt = 0; nt < 8; nt++) {
            int c = wn + nt * 8 + (lane & 3) * 2;
#pragma unroll
            for (int hh = 0; hh < 2; hh++) {
                int r = r0 + hh * 8;
                if (r >= NN) continue;
                float v0 = acc[m][nt][hh * 2 + 0];
                float v1 = acc[m][nt][hh * 2 + 1];
                if (MODE == 0 || MODE == 1) {
                    v0 += bias[c];
                    v1 += bias[c + 1];
                    float2 mv = *reinterpret_cast<const float2*>(mask + (size_t)r * 128 + c);
                    v0 = fmaxf(v0, 0.f) * mv.x;
                    v1 = fmaxf(v1, 0.f) * mv.y;
                    *reinterpret_cast<float2*>(out + (size_t)r * 128 + c) = make_float2(v0, v1);
                    if (MODE == 0)
                        *reinterpret_cast<__half2*>(h16out + (size_t)r * 128 + c) =
                            __floats2half2_rn(v0, v1);
                } else {
                    if (c < 64) {
                        v0 += bias[c];
                        v1 += bias[c + 1];
                        *reinterpret_cast<float2*>(out + (size_t)r * 64 + c) = make_float2(v0, v1);
                    } else {
                        *reinterpret_cast<__half2*>(h16out + (size_t)r * 64 + (c - 64)) =
                            __floats2half2_rn(v0, v1);
                    }
                }
            }
        }
    }
}

// ---------------- launch ----------------
extern "C" void kernel_launch(void* const* d_in, const int* in_sizes, int n_in,
                              void* d_out, int out_size) {
    const float* x   = (const float*)d_in[0];
    const int*   src = (const int*)d_in[1];
    const int*   dst = (const int*)d_in[2];
    const float* Ws1 = (const float*)d_in[3];
    const float* Wn1 = (const float*)d_in[4];
    const float* b1  = (const float*)d_in[5];
    const float* Ws2 = (const float*)d_in[6];
    const float* Wn2 = (const float*)d_in[7];
    const float* b2  = (const float*)d_in[8];
    const float* Ws3 = (const float*)d_in[9];
    const float* Wn3 = (const float*)d_in[10];
    const float* b3  = (const float*)d_in[11];
    const float* m1  = (const float*)d_in[12];
    const float* m2  = (const float*)d_in[13];
    float* out = (float*)d_out;

    // Real DEVICE addresses (host symbol = ATS shadow trap, see R1)
    float *hA = nullptr, *hB = nullptr, *neigh = nullptr;
    __half* h16 = nullptr;
    __nv_bfloat16 *Bhi = nullptr, *Blo = nullptr;
    cudaGetSymbolAddress((void**)&hA, g_hA);
    cudaGetSymbolAddress((void**)&hB, g_hB);
    cudaGetSymbolAddress((void**)&neigh, g_neigh);
    cudaGetSymbolAddress((void**)&h16, g_h16);
    cudaGetSymbolAddress((void**)&Bhi, g_Bhi);
    cudaGetSymbolAddress((void**)&Blo, g_Blo);

    constexpr int SMEM_GEMM = 8 * 128 * 40 * 2;  // 81920 B
    cudaFuncSetAttribute(sage_mma_kernel<8, true, 0>,
                         cudaFuncAttributeMaxDynamicSharedMemorySize, SMEM_GEMM);
    cudaFuncSetAttribute(sage_mma_kernel<8, true, 1>,
                         cudaFuncAttributeMaxDynamicSharedMemorySize, SMEM_GEMM);
    cudaFuncSetAttribute(sage_mma_kernel<4, false, 2>,
                         cudaFuncAttributeMaxDynamicSharedMemorySize, SMEM_GEMM);

    // ---- weight prep (bf16 hi/lo, transposed) ----
    prep_B_kernel<<<(128 * 256 + 255) / 256, 256>>>(Ws1, Wn1, Bhi, Blo, 0);
    prep_B_kernel<<<(128 * 256 + 255) / 256, 256>>>(Ws2, Wn2, Bhi + 32768, Blo + 32768, 0);
    prep_B_kernel<<<(128 * 128 + 255) / 256, 256>>>(Ws3, Wn3, Bhi + 65536, Blo + 65536, 1);

    // ---- x -> fp16 mirror (16B-vectorized) ----
    conv16_kernel<<<(NN * 32 + 255) / 256, 256>>>((const float4*)x, (uint2*)h16, NN * 32);

    // ---- CSR build ----
    zero_kernel<<<(NN + 255) / 256, 256>>>();
    count_kernel<<<(EE + 255) / 256, 256>>>(dst);
    scan_partials<<<NBLK, 256>>>();
    scan_bsums<<<1, 256>>>();
    scan_final<<<NBLK, 256>>>();
    fill_kernel<<<(EE + 255) / 256, 256>>>(src, dst);

    int tiles = (NN + 127) / 128;            // 391
    int aggBlocks = (NN * 32 + 255) / 256;

    // ---- layer 1 ----
    agg_h16_kernel<<<aggBlocks, 256>>>(h16, neigh);   // gathers x16
    sage_mma_kernel<8, true, 0><<<tiles, 256, SMEM_GEMM>>>(x, neigh, Bhi, Blo, b1, m1, hA, h16); // writes hA + hA16

    // ---- layer 2 ----
    agg_h16_kernel<<<aggBlocks, 256>>>(h16, neigh);   // gathers hA16
    sage_mma_kernel<8, true, 1><<<tiles, 256, SMEM_GEMM>>>(hA, neigh, Bhi + 32768, Blo + 32768, b2, m2, hB, nullptr);

    // ---- layer 3: project (self fp32 -> hA, proj fp16 -> h16), then aggregate ----
    sage_mma_kernel<4, false, 2><<<tiles, 256, SMEM_GEMM>>>(hB, nullptr, Bhi + 65536, Blo + 65536, b3, nullptr, hA, h16);
    agg3_h16_kernel<<<aggBlocks, 256>>>(h16, hA, out);
}

// round 9
// speedup vs baseline: 1.3018x; 1.3018x over previous
#include <cuda_runtime.h>
#include <cuda_fp16.h>
#include <cstdint>

#define NN 50000
#define EE 800000
#define NBLK 196   // ceil(NN/256)

// ---------------- device scratch (all-fp16 activation pipeline) ----------------
__device__ __half g_x16[NN * 128];    // x mirror; reused as layer-3 proj p16 [NN*64]
__device__ __half g_hA16[NN * 128];   // layer-1 activations
__device__ __half g_hB16[NN * 128];   // layer-2 activations
__device__ __half g_n16[NN * 128];    // aggregated neighbor features
__device__ float  g_self[NN * 64];    // layer-3 self projection (fp32)
__device__ int   g_deg[NN];
__device__ int   g_off[NN + 1];
__device__ int   g_cur[NN];
__device__ int   g_csr[EE];
__device__ int   g_bsum[256];
__device__ int   g_boff[256];
__device__ __half g_B16[3 * 128 * 256]; // transposed fp16 weights, 3 layers

// ---------------- helpers ----------------
__device__ __forceinline__ uint32_t smem_u32(const void* p) {
    uint32_t a;
    asm("{ .reg .u64 t; cvta.to.shared.u64 t, %1; cvt.u32.u64 %0, t; }" : "=r"(a) : "l"(p));
    return a;
}
__device__ __forceinline__ void mma_f16(float* d, const uint32_t* a, const uint32_t* b) {
    asm volatile(
        "mma.sync.aligned.m16n8k16.row.col.f32.f16.f16.f32 "
        "{%0,%1,%2,%3}, {%4,%5,%6,%7}, {%8,%9}, {%0,%1,%2,%3};"
        : "+f"(d[0]), "+f"(d[1]), "+f"(d[2]), "+f"(d[3])
        : "r"(a[0]), "r"(a[1]), "r"(a[2]), "r"(a[3]), "r"(b[0]), "r"(b[1]));
}
__device__ __forceinline__ void ldsm_x4(uint32_t* r, uint32_t addr) {
    asm volatile("ldmatrix.sync.aligned.m8n8.x4.shared.b16 {%0,%1,%2,%3}, [%4];"
                 : "=r"(r[0]), "=r"(r[1]), "=r"(r[2]), "=r"(r[3]) : "r"(addr));
}

// ---------------- prep: all 3 weight sets -> transposed fp16 (one launch) ----------------
// Layer1/2: B[n][k], k in [0,256): k<128 from Ws[k*128+n], else Wn[(k-128)*128+n]
// Layer3:   B[n][k], k in [0,128): n<64 -> Ws3[k*64+n], n>=64 -> Wn3[k*64+n-64]
__global__ void prep_all_kernel(const float* __restrict__ Ws1, const float* __restrict__ Wn1,
                                const float* __restrict__ Ws2, const float* __restrict__ Wn2,
                                const float* __restrict__ Ws3, const float* __restrict__ Wn3,
                                __half* __restrict__ B16) {
    int idx = blockIdx.x * blockDim.x + threadIdx.x;
    if (idx < 2 * 128 * 256) {
        int layer = idx >> 15;          // /32768
        int li = idx & 32767;
        int n = li >> 8, k = li & 255;
        const float* W1 = layer ? Ws2 : Ws1;
        const float* W2 = layer ? Wn2 : Wn1;
        float w = (k < 128) ? W1[k * 128 + n] : W2[(k - 128) * 128 + n];
        B16[idx] = __float2half_rn(w);
    } else if (idx < 2 * 128 * 256 + 128 * 128) {
        int li = idx - 2 * 128 * 256;
        int n = li >> 7, k = li & 127;
        float w = (n < 64) ? Ws3[k * 64 + n] : Wn3[k * 64 + (n - 64)];
        // layer-3 stored with KTOT=128 stride
        B16[2 * 128 * 256 + n * 128 + k] = __float2half_rn(w);
    }
}

// ---------------- fp32 -> fp16 convert (16B loads) ----------------
__global__ void conv16_kernel(const float4* __restrict__ src, uint2* __restrict__ dst, int n4) {
    int i = blockIdx.x * blockDim.x + threadIdx.x;
    if (i < n4) {
        float4 v = src[i];
        __half2 h0 = __floats2half2_rn(v.x, v.y);
        __half2 h1 = __floats2half2_rn(v.z, v.w);
        dst[i] = make_uint2(*reinterpret_cast<uint32_t*>(&h0), *reinterpret_cast<uint32_t*>(&h1));
    }
}

// ---------------- CSR build ----------------
__global__ void zero_kernel() {
    int i = blockIdx.x * blockDim.x + threadIdx.x;
    if (i < NN) g_deg[i] = 0;
}
__global__ void count_kernel(const int* __restrict__ dst) {
    int e = blockIdx.x * blockDim.x + threadIdx.x;
    if (e < EE) atomicAdd(&g_deg[dst[e]], 1);
}
__global__ void scan_partials() {
    __shared__ int sh[256];
    int t = threadIdx.x;
    int i = blockIdx.x * 256 + t;
    sh[t] = (i < NN) ? g_deg[i] : 0;
    __syncthreads();
    for (int o = 128; o > 0; o >>= 1) {
        if (t < o) sh[t] += sh[t + o];
        __syncthreads();
    }
    if (t == 0) g_bsum[blockIdx.x] = sh[0];
}
__global__ void scan_bsums() {
    __shared__ int sh[256];
    int t = threadIdx.x;
    int v = (t < NBLK) ? g_bsum[t] : 0;
    sh[t] = v;
    __syncthreads();
    for (int o = 1; o < 256; o <<= 1) {
        int x = (t >= o) ? sh[t - o] : 0;
        __syncthreads();
        sh[t] += x;
        __syncthreads();
    }
    if (t < NBLK) g_boff[t] = sh[t] - v;   // exclusive
}
__global__ void scan_final() {
    __shared__ int sh[256];
    int t = threadIdx.x;
    int i = blockIdx.x * 256 + t;
    int v = (i < NN) ? g_deg[i] : 0;
    sh[t] = v;
    __syncthreads();
    for (int o = 1; o < 256; o <<= 1) {
        int x = (t >= o) ? sh[t - o] : 0;
        __syncthreads();
        sh[t] += x;
        __syncthreads();
    }
    int off = g_boff[blockIdx.x] + sh[t] - v;   // exclusive
    if (i <= NN) g_off[i] = off;
    if (i < NN) g_cur[i] = off;                  // fill bumps this directly
}
__global__ void fill_kernel(const int* __restrict__ src, const int* __restrict__ dst) {
    int e = blockIdx.x * blockDim.x + threadIdx.x;
    if (e < EE) {
        int pos = atomicAdd(&g_cur[dst[e]], 1);
        g_csr[pos] = src[e];
    }
}

// ---------------- mean aggregation (128-dim): warp per node, fp16 in/out ----------------
__global__ void agg16_kernel(const __half* __restrict__ h16, __half* __restrict__ n16) {
    int gt = blockIdx.x * blockDim.x + threadIdx.x;
    int node = gt >> 5;
    int lane = gt & 31;
    if (node >= NN) return;
    int s = g_off[node], e = g_off[node + 1];
    float a0 = 0.f, a1 = 0.f, a2 = 0.f, a3 = 0.f;
    int j = s;
    for (; j + 4 <= e; j += 4) {
        int i0 = g_csr[j], i1 = g_csr[j + 1], i2 = g_csr[j + 2], i3 = g_csr[j + 3];
        uint2 v0 = *reinterpret_cast<const uint2*>(h16 + (size_t)i0 * 128 + lane * 4);
        uint2 v1 = *reinterpret_cast<const uint2*>(h16 + (size_t)i1 * 128 + lane * 4);
        uint2 v2 = *reinterpret_cast<const uint2*>(h16 + (size_t)i2 * 128 + lane * 4);
        uint2 v3 = *reinterpret_cast<const uint2*>(h16 + (size_t)i3 * 128 + lane * 4);
        float2 f;
        f = __half22float2(*reinterpret_cast<__half2*>(&v0.x)); a0 += f.x; a1 += f.y;
        f = __half22float2(*reinterpret_cast<__half2*>(&v0.y)); a2 += f.x; a3 += f.y;
        f = __half22float2(*reinterpret_cast<__half2*>(&v1.x)); a0 += f.x; a1 += f.y;
        f = __half22float2(*reinterpret_cast<__half2*>(&v1.y)); a2 += f.x; a3 += f.y;
        f = __half22float2(*reinterpret_cast<__half2*>(&v2.x)); a0 += f.x; a1 += f.y;
        f = __half22float2(*reinterpret_cast<__half2*>(&v2.y)); a2 += f.x; a3 += f.y;
        f = __half22float2(*reinterpret_cast<__half2*>(&v3.x)); a0 += f.x; a1 += f.y;
        f = __half22float2(*reinterpret_cast<__half2*>(&v3.y)); a2 += f.x; a3 += f.y;
    }
    for (; j < e; j++) {
        int sidx = g_csr[j];
        uint2 v = *reinterpret_cast<const uint2*>(h16 + (size_t)sidx * 128 + lane * 4);
        float2 f0 = __half22float2(*reinterpret_cast<__half2*>(&v.x));
        float2 f1 = __half22float2(*reinterpret_cast<__half2*>(&v.y));
        a0 += f0.x; a1 += f0.y; a2 += f1.x; a3 += f1.y;
    }
    float inv = 1.0f / (float)max(e - s, 1);
    __half2 o0 = __floats2half2_rn(a0 * inv, a1 * inv);
    __half2 o1 = __floats2half2_rn(a2 * inv, a3 * inv);
    *reinterpret_cast<uint2*>(n16 + (size_t)node * 128 + lane * 4) =
        make_uint2(*reinterpret_cast<uint32_t*>(&o0), *reinterpret_cast<uint32_t*>(&o1));
}

// ---------------- layer-3 final: out = self + mean(proj16[src]) ----------------
__global__ void agg3_kernel(const __half* __restrict__ p16, const float* __restrict__ self,
                            float* __restrict__ out) {
    int gt = blockIdx.x * blockDim.x + threadIdx.x;
    int node = gt >> 5;
    int lane = gt & 31;
    if (node >= NN) return;
    int s = g_off[node], e = g_off[node + 1];
    float a0 = 0.f, a1 = 0.f;
    int j = s;
    for (; j + 4 <= e; j += 4) {
        int i0 = g_csr[j], i1 = g_csr[j + 1], i2 = g_csr[j + 2], i3 = g_csr[j + 3];
        uint32_t v0 = *reinterpret_cast<const uint32_t*>(p16 + (size_t)i0 * 64 + lane * 2);
        uint32_t v1 = *reinterpret_cast<const uint32_t*>(p16 + (size_t)i1 * 64 + lane * 2);
        uint32_t v2 = *reinterpret_cast<const uint32_t*>(p16 + (size_t)i2 * 64 + lane * 2);
        uint32_t v3 = *reinterpret_cast<const uint32_t*>(p16 + (size_t)i3 * 64 + lane * 2);
        float2 f;
        f = __half22float2(*reinterpret_cast<__half2*>(&v0)); a0 += f.x; a1 += f.y;
        f = __half22float2(*reinterpret_cast<__half2*>(&v1)); a0 += f.x; a1 += f.y;
        f = __half22float2(*reinterpret_cast<__half2*>(&v2)); a0 += f.x; a1 += f.y;
        f = __half22float2(*reinterpret_cast<__half2*>(&v3)); a0 += f.x; a1 += f.y;
    }
    for (; j < e; j++) {
        int sidx = g_csr[j];
        uint32_t v = *reinterpret_cast<const uint32_t*>(p16 + (size_t)sidx * 64 + lane * 2);
        float2 f = __half22float2(*reinterpret_cast<__half2*>(&v));
        a0 += f.x; a1 += f.y;
    }
    float inv = 1.0f / (float)max(e - s, 1);
    float2 sv = *reinterpret_cast<const float2*>(self + (size_t)node * 64 + lane * 2);
    *reinterpret_cast<float2*>(out + (size_t)node * 64 + lane * 2) =
        make_float2(sv.x + a0 * inv, sv.y + a1 * inv);
}

// ---------------- single-pass fp16 tensor-core GEMM (fp32 accum) ----------------
// MODE 0: relu*mask epilogue, fp16 128-wide output (layers 1,2)
// MODE 2: layer-3 split: cols<64 -> self fp32 (+bias), cols>=64 -> p16 fp16 (no bias)
template <int KCHUNKS, bool DUAL, int MODE>
__global__ void __launch_bounds__(256, 2)
sage_mma_kernel(const __half* __restrict__ A0, const __half* __restrict__ A1,
                const __half* __restrict__ B16,
                const float* __restrict__ bias, const float* __restrict__ mask,
                float* __restrict__ out, __half* __restrict__ h16out) {
    constexpr int PAD = 40;                 // halves per smem row (80B: conflict-free ldmatrix)
    constexpr int KTOT = KCHUNKS * 32;
    constexpr int BUFH = 128 * PAD;
    extern __shared__ uint16_t sm[];
    const uint32_t base = smem_u32(sm);
    uint16_t* sA = sm;                      // [2][128][PAD]
    uint16_t* sB = sm + 2 * BUFH;           // [2][128][PAD]

    const int tid = threadIdx.x, lane = tid & 31, wid = tid >> 5;
    const int bm = blockIdx.x * 128;
    const int wm = (wid & 3) * 32;          // 4 warps down M
    const int wn = (wid >> 2) * 64;         // 2 warps across N

    float acc[2][8][4];
#pragma unroll
    for (int m = 0; m < 2; m++)
#pragma unroll
        for (int n = 0; n < 8; n++)
#pragma unroll
            for (int i = 0; i < 4; i++) acc[m][n][i] = 0.f;

    uint4 pa[2], pb[2];
    auto loadAB = [&](int ch) {
        const __half* asrc = DUAL ? (ch < KCHUNKS / 2 ? A0 : A1) : A0;
        int klocal = DUAL ? (ch & (KCHUNKS / 2 - 1)) * 32 : ch * 32;
        int k0 = ch * 32;
#pragma unroll
        for (int j = 0; j < 2; j++) {
            int item = tid + j * 256;
            int row = item >> 2, q = item & 3;
            int grow = bm + row;
            pa[j] = (grow < NN)
                ? *reinterpret_cast<const uint4*>(asrc + (size_t)grow * 128 + klocal + q * 8)
                : make_uint4(0, 0, 0, 0);
            pb[j] = *reinterpret_cast<const uint4*>(B16 + row * KTOT + k0 + q * 8);
        }
    };
    auto storeAB = [&](int buf) {
#pragma unroll
        for (int j = 0; j < 2; j++) {
            int item = tid + j * 256;
            int row = item >> 2, q = item & 3;
            int off = buf * BUFH + row * PAD + q * 8;
            *reinterpret_cast<uint4*>(&sA[off]) = pa[j];
            *reinterpret_cast<uint4*>(&sB[off]) = pb[j];
        }
    };

    loadAB(0);
    storeAB(0);

    for (int ch = 0; ch < KCHUNKS; ch++) {
        __syncthreads();
        int buf = ch & 1;
        bool more = (ch + 1 < KCHUNKS);
        if (more) loadAB(ch + 1);   // LDGs in flight during MMA work

#pragma unroll
        for (int ks = 0; ks < 2; ks++) {
            uint32_t ah[2][4];
            int arow = wm + (lane & 7) + ((lane >> 3) & 1) * 8;
            int acol = ks * 16 + (lane >> 4) * 8;
#pragma unroll
            for (int m = 0; m < 2; m++) {
                uint32_t aoff = (uint32_t)(buf * BUFH + (arow + m * 16) * PAD + acol) * 2;
                ldsm_x4(ah[m], base + aoff);
            }
            int brow = wn + (lane & 7) + ((lane >> 4) & 1) * 8;
            int bcol = ks * 16 + ((lane >> 3) & 1) * 8;
#pragma unroll
            for (int nt2 = 0; nt2 < 4; nt2++) {
                uint32_t bh[4];
                uint32_t boff = (uint32_t)((2 + buf) * BUFH + (brow + nt2 * 16) * PAD + bcol) * 2;
                ldsm_x4(bh, base + boff);
#pragma unroll
                for (int m = 0; m < 2; m++) {
                    mma_f16(acc[m][nt2 * 2], ah[m], &bh[0]);
                    mma_f16(acc[m][nt2 * 2 + 1], ah[m], &bh[2]);
                }
            }
        }
        if (more) storeAB(buf ^ 1);
    }

    // ---- epilogue ----
#pragma unroll
    for (int m = 0; m < 2; m++) {
        int r0 = bm + wm + m * 16 + (lane >> 2);
#pragma unroll
        for (int nt = 0; nt < 8; nt++) {
            int c = wn + nt * 8 + (lane & 3) * 2;
#pragma unroll
            for (int hh = 0; hh < 2; hh++) {
                int r = r0 + hh * 8;
                if (r >= NN) continue;
                float v0 = acc[m][nt][hh * 2 + 0];
                float v1 = acc[m][nt][hh * 2 + 1];
                if (MODE == 0) {
                    v0 += bias[c];
                    v1 += bias[c + 1];
                    float2 mv = *reinterpret_cast<const float2*>(mask + (size_t)r * 128 + c);
                    v0 = fmaxf(v0, 0.f) * mv.x;
                    v1 = fmaxf(v1, 0.f) * mv.y;
                    *reinterpret_cast<__half2*>(h16out + (size_t)r * 128 + c) =
                        __floats2half2_rn(v0, v1);
                } else {
                    if (c < 64) {
                        v0 += bias[c];
                        v1 += bias[c + 1];
                        *reinterpret_cast<float2*>(out + (size_t)r * 64 + c) = make_float2(v0, v1);
                    } else {
                        *reinterpret_cast<__half2*>(h16out + (size_t)r * 64 + (c - 64)) =
                            __floats2half2_rn(v0, v1);
                    }
                }
            }
        }
    }
}

// ---------------- launch ----------------
extern "C" void kernel_launch(void* const* d_in, const int* in_sizes, int n_in,
                              void* d_out, int out_size) {
    const float* x   = (const float*)d_in[0];
    const int*   src = (const int*)d_in[1];
    const int*   dst = (const int*)d_in[2];
    const float* Ws1 = (const float*)d_in[3];
    const float* Wn1 = (const float*)d_in[4];
    const float* b1  = (const float*)d_in[5];
    const float* Ws2 = (const float*)d_in[6];
    const float* Wn2 = (const float*)d_in[7];
    const float* b2  = (const float*)d_in[8];
    const float* Ws3 = (const float*)d_in[9];
    const float* Wn3 = (const float*)d_in[10];
    const float* b3  = (const float*)d_in[11];
    const float* m1  = (const float*)d_in[12];
    const float* m2  = (const float*)d_in[13];
    float* out = (float*)d_out;

    // Real DEVICE addresses (host symbol = ATS shadow trap, see R1)
    __half *x16 = nullptr, *hA16 = nullptr, *hB16 = nullptr, *n16 = nullptr, *B16 = nullptr;
    float* selfp = nullptr;
    cudaGetSymbolAddress((void**)&x16, g_x16);
    cudaGetSymbolAddress((void**)&hA16, g_hA16);
    cudaGetSymbolAddress((void**)&hB16, g_hB16);
    cudaGetSymbolAddress((void**)&n16, g_n16);
    cudaGetSymbolAddress((void**)&B16, g_B16);
    cudaGetSymbolAddress((void**)&selfp, g_self);

    constexpr int SMEM_GEMM = 4 * 128 * 40 * 2;  // 40960 B
    cudaFuncSetAttribute(sage_mma_kernel<8, true, 0>,
                         cudaFuncAttributeMaxDynamicSharedMemorySize, SMEM_GEMM);
    cudaFuncSetAttribute(sage_mma_kernel<4, false, 2>,
                         cudaFuncAttributeMaxDynamicSharedMemorySize, SMEM_GEMM);

    // ---- weight prep (single launch) + x -> fp16 mirror ----
    prep_all_kernel<<<(2 * 128 * 256 + 128 * 128 + 255) / 256, 256>>>(Ws1, Wn1, Ws2, Wn2, Ws3, Wn3, B16);
    conv16_kernel<<<(NN * 32 + 255) / 256, 256>>>((const float4*)x, (uint2*)x16, NN * 32);

    // ---- CSR build ----
    zero_kernel<<<(NN + 255) / 256, 256>>>();
    count_kernel<<<(EE + 255) / 256, 256>>>(dst);
    scan_partials<<<NBLK, 256>>>();
    scan_bsums<<<1, 256>>>();
    scan_final<<<NBLK, 256>>>();
    fill_kernel<<<(EE + 255) / 256, 256>>>(src, dst);

    int tiles = (NN + 127) / 128;            // 391
    int aggBlocks = (NN * 32 + 255) / 256;

    // ---- layer 1 ----
    agg16_kernel<<<aggBlocks, 256>>>(x16, n16);
    sage_mma_kernel<8, true, 0><<<tiles, 256, SMEM_GEMM>>>(x16, n16, B16, b1, m1, nullptr, hA16);

    // ---- layer 2 ----
    agg16_kernel<<<aggBlocks, 256>>>(hA16, n16);
    sage_mma_kernel<8, true, 0><<<tiles, 256, SMEM_GEMM>>>(hA16, n16, B16 + 32768, b2, m2, nullptr, hB16);

    // ---- layer 3: project (self fp32, proj fp16 into x16), then aggregate ----
    sage_mma_kernel<4, false, 2><<<tiles, 256, SMEM_GEMM>>>(hB16, nullptr, B16 + 65536, b3, nullptr, selfp, x16);
    agg3_kernel<<<aggBlocks, 256>>>(x16, selfp, out);
}